// round 1
// baseline (speedup 1.0000x reference)
#include <cuda_runtime.h>
#include <math.h>

#define BATCH 8
#define LSEQ  2048
#define DDIM  512

// Scratch for the 8 x 2048 x 2048 logits/attention matrix (128 MiB).
// __device__ global: module-load allocation, not a runtime alloc.
static __device__ float g_P[(size_t)BATCH * LSEQ * LSEQ];

// ---------------------------------------------------------------------------
// Kernel 1: P[b,i,j] = scale * sum_d (x[b,i,d]*qw[i,d]) * (x[b,j,d]*kw[j,d])
// 128x128 block tile, 256 threads, 8x8 per-thread microtile, K-chunk 8,
// double-buffered shared memory. Elementwise projections fused into loads.
// ---------------------------------------------------------------------------
__global__ __launch_bounds__(256) void qk_kernel(const float* __restrict__ x,
                                                 const float* __restrict__ qw,
                                                 const float* __restrict__ kw)
{
    __shared__ __align__(16) float As[2][8][128];
    __shared__ __align__(16) float Bs[2][8][128];

    const int b  = blockIdx.z;
    const int m0 = blockIdx.y * 128;
    const int n0 = blockIdx.x * 128;
    const int t  = threadIdx.x;
    const int tx = t & 15;        // 0..15 -> output cols (8 each)
    const int ty = t >> 4;        // 0..15 -> output rows (8 each)
    const int lr = t >> 1;        // load row 0..127
    const int lc = (t & 1) * 4;   // load col 0 or 4 within the 8-wide K chunk

    const float* xa = x  + ((size_t)b * LSEQ + (m0 + lr)) * DDIM;
    const float* xb = x  + ((size_t)b * LSEQ + (n0 + lr)) * DDIM;
    const float* qa = qw + (size_t)(m0 + lr) * DDIM;
    const float* kb = kw + (size_t)(n0 + lr) * DDIM;

    float acc[8][8];
#pragma unroll
    for (int i = 0; i < 8; ++i)
#pragma unroll
        for (int j = 0; j < 8; ++j) acc[i][j] = 0.0f;

    // preload chunk 0
    {
        float4 ax = *(const float4*)(xa + lc);
        float4 aq = *(const float4*)(qa + lc);
        float4 bx = *(const float4*)(xb + lc);
        float4 bk = *(const float4*)(kb + lc);
        As[0][lc + 0][lr] = ax.x * aq.x;
        As[0][lc + 1][lr] = ax.y * aq.y;
        As[0][lc + 2][lr] = ax.z * aq.z;
        As[0][lc + 3][lr] = ax.w * aq.w;
        Bs[0][lc + 0][lr] = bx.x * bk.x;
        Bs[0][lc + 1][lr] = bx.y * bk.y;
        Bs[0][lc + 2][lr] = bx.z * bk.z;
        Bs[0][lc + 3][lr] = bx.w * bk.w;
    }
    __syncthreads();

    const int NK = DDIM / 8;   // 64
    for (int c = 0; c < NK; ++c) {
        const int cur = c & 1;
        float4 ax, aq, bx, bk;
        const bool more = (c + 1) < NK;
        if (more) {
            const int off = (c + 1) * 8 + lc;
            ax = *(const float4*)(xa + off);
            aq = *(const float4*)(qa + off);
            bx = *(const float4*)(xb + off);
            bk = *(const float4*)(kb + off);
        }

#pragma unroll
        for (int k = 0; k < 8; ++k) {
            float a[8], bb[8];
            *(float4*)(a)      = *(const float4*)&As[cur][k][ty * 8];
            *(float4*)(a + 4)  = *(const float4*)&As[cur][k][ty * 8 + 4];
            *(float4*)(bb)     = *(const float4*)&Bs[cur][k][tx * 8];
            *(float4*)(bb + 4) = *(const float4*)&Bs[cur][k][tx * 8 + 4];
#pragma unroll
            for (int i = 0; i < 8; ++i)
#pragma unroll
                for (int j = 0; j < 8; ++j) acc[i][j] += a[i] * bb[j];
        }

        if (more) {
            const int nxt = cur ^ 1;
            As[nxt][lc + 0][lr] = ax.x * aq.x;
            As[nxt][lc + 1][lr] = ax.y * aq.y;
            As[nxt][lc + 2][lr] = ax.z * aq.z;
            As[nxt][lc + 3][lr] = ax.w * aq.w;
            Bs[nxt][lc + 0][lr] = bx.x * bk.x;
            Bs[nxt][lc + 1][lr] = bx.y * bk.y;
            Bs[nxt][lc + 2][lr] = bx.z * bk.z;
            Bs[nxt][lc + 3][lr] = bx.w * bk.w;
        }
        __syncthreads();
    }

    // scale = 1/sqrt(KEY_SIZE=8)
    const float scale = 0.3535533905932738f;
    float* P = g_P + ((size_t)b * LSEQ + (m0 + ty * 8)) * LSEQ + n0 + tx * 8;
#pragma unroll
    for (int i = 0; i < 8; ++i) {
        float4 v0, v1;
        v0.x = acc[i][0] * scale; v0.y = acc[i][1] * scale;
        v0.z = acc[i][2] * scale; v0.w = acc[i][3] * scale;
        v1.x = acc[i][4] * scale; v1.y = acc[i][5] * scale;
        v1.z = acc[i][6] * scale; v1.w = acc[i][7] * scale;
        *(float4*)(P + (size_t)i * LSEQ)     = v0;
        *(float4*)(P + (size_t)i * LSEQ + 4) = v1;
    }
}

// ---------------------------------------------------------------------------
// Kernel 2: row softmax over g_P (in place). One block per row.
// ---------------------------------------------------------------------------
__global__ __launch_bounds__(256) void softmax_kernel()
{
    const size_t row = blockIdx.x;
    float* p = g_P + row * LSEQ;
    const int t = threadIdx.x;

    __shared__ float red[256];

    float v[8];
    float mx = -1e30f;
#pragma unroll
    for (int i = 0; i < 8; ++i) {
        v[i] = p[t + i * 256];
        mx = fmaxf(mx, v[i]);
    }
    red[t] = mx;
    __syncthreads();
    for (int s = 128; s > 0; s >>= 1) {
        if (t < s) red[t] = fmaxf(red[t], red[t + s]);
        __syncthreads();
    }
    const float m = red[0];
    __syncthreads();

    float sum = 0.0f;
#pragma unroll
    for (int i = 0; i < 8; ++i) {
        v[i] = __expf(v[i] - m);
        sum += v[i];
    }
    red[t] = sum;
    __syncthreads();
    for (int s = 128; s > 0; s >>= 1) {
        if (t < s) red[t] += red[t + s];
        __syncthreads();
    }
    const float inv = 1.0f / red[0];
#pragma unroll
    for (int i = 0; i < 8; ++i) p[t + i * 256] = v[i] * inv;
}

// ---------------------------------------------------------------------------
// Kernel 3: out[b,i,d] = sum_j A[b,i,j] * (x[b,j,d]*vw[j,d])
// Same SGEMM structure; B-tile is row-major in d (direct float4 stores).
// ---------------------------------------------------------------------------
__global__ __launch_bounds__(256) void av_kernel(const float* __restrict__ x,
                                                 const float* __restrict__ vw,
                                                 float* __restrict__ out)
{
    __shared__ __align__(16) float As[2][8][128];
    __shared__ __align__(16) float Bs[2][8][128];

    const int b  = blockIdx.z;
    const int m0 = blockIdx.y * 128;       // query rows
    const int n0 = blockIdx.x * 128;       // feature cols (D)
    const int t  = threadIdx.x;
    const int tx = t & 15;
    const int ty = t >> 4;

    // A-tile loader: 128 rows x 8 cols of attention
    const int lr = t >> 1;
    const int lc = (t & 1) * 4;
    const float* Arow = g_P + ((size_t)b * LSEQ + (m0 + lr)) * LSEQ;

    // B-tile loader: 8 j-rows x 128 d-cols of v = x*vw
    const int lk = t >> 5;          // 0..7
    const int ln = (t & 31) * 4;    // 0..124

    float acc[8][8];
#pragma unroll
    for (int i = 0; i < 8; ++i)
#pragma unroll
        for (int j = 0; j < 8; ++j) acc[i][j] = 0.0f;

    // preload chunk 0
    {
        float4 a4 = *(const float4*)(Arow + lc);
        As[0][lc + 0][lr] = a4.x;
        As[0][lc + 1][lr] = a4.y;
        As[0][lc + 2][lr] = a4.z;
        As[0][lc + 3][lr] = a4.w;
        float4 xv = *(const float4*)(x  + ((size_t)b * LSEQ + lk) * DDIM + n0 + ln);
        float4 wv = *(const float4*)(vw + (size_t)lk * DDIM + n0 + ln);
        float4 bv;
        bv.x = xv.x * wv.x; bv.y = xv.y * wv.y; bv.z = xv.z * wv.z; bv.w = xv.w * wv.w;
        *(float4*)&Bs[0][lk][ln] = bv;
    }
    __syncthreads();

    const int NK = LSEQ / 8;   // 256
    for (int c = 0; c < NK; ++c) {
        const int cur = c & 1;
        float4 a4, xv, wv;
        const bool more = (c + 1) < NK;
        if (more) {
            const int kk = (c + 1) * 8;
            a4 = *(const float4*)(Arow + kk + lc);
            xv = *(const float4*)(x  + ((size_t)b * LSEQ + kk + lk) * DDIM + n0 + ln);
            wv = *(const float4*)(vw + (size_t)(kk + lk) * DDIM + n0 + ln);
        }

#pragma unroll
        for (int k = 0; k < 8; ++k) {
            float a[8], bb[8];
            *(float4*)(a)      = *(const float4*)&As[cur][k][ty * 8];
            *(float4*)(a + 4)  = *(const float4*)&As[cur][k][ty * 8 + 4];
            *(float4*)(bb)     = *(const float4*)&Bs[cur][k][tx * 8];
            *(float4*)(bb + 4) = *(const float4*)&Bs[cur][k][tx * 8 + 4];
#pragma unroll
            for (int i = 0; i < 8; ++i)
#pragma unroll
                for (int j = 0; j < 8; ++j) acc[i][j] += a[i] * bb[j];
        }

        if (more) {
            const int nxt = cur ^ 1;
            As[nxt][lc + 0][lr] = a4.x;
            As[nxt][lc + 1][lr] = a4.y;
            As[nxt][lc + 2][lr] = a4.z;
            As[nxt][lc + 3][lr] = a4.w;
            float4 bv;
            bv.x = xv.x * wv.x; bv.y = xv.y * wv.y; bv.z = xv.z * wv.z; bv.w = xv.w * wv.w;
            *(float4*)&Bs[nxt][lk][ln] = bv;
        }
        __syncthreads();
    }

    float* O = out + ((size_t)b * LSEQ + (m0 + ty * 8)) * DDIM + n0 + tx * 8;
#pragma unroll
    for (int i = 0; i < 8; ++i) {
        float4 v0, v1;
        v0.x = acc[i][0]; v0.y = acc[i][1]; v0.z = acc[i][2]; v0.w = acc[i][3];
        v1.x = acc[i][4]; v1.y = acc[i][5]; v1.z = acc[i][6]; v1.w = acc[i][7];
        *(float4*)(O + (size_t)i * DDIM)     = v0;
        *(float4*)(O + (size_t)i * DDIM + 4) = v1;
    }
}

extern "C" void kernel_launch(void* const* d_in, const int* in_sizes, int n_in,
                              void* d_out, int out_size)
{
    const float* x  = (const float*)d_in[0];   // (8, 2048, 512)
    const float* qw = (const float*)d_in[1];   // (2048, 512)
    const float* kw = (const float*)d_in[2];   // (2048, 512)
    const float* vw = (const float*)d_in[3];   // (2048, 512)
    float* out = (float*)d_out;                // (8, 2048, 512)

    dim3 g1(LSEQ / 128, LSEQ / 128, BATCH);    // 16 x 16 x 8
    qk_kernel<<<g1, 256>>>(x, qw, kw);

    softmax_kernel<<<BATCH * LSEQ, 256>>>();

    dim3 g3(DDIM / 128, LSEQ / 128, BATCH);    // 4 x 16 x 8
    av_kernel<<<g3, 256>>>(x, vw, out);
}

// round 3
// speedup vs baseline: 2.5323x; 2.5323x over previous
#include <cuda_runtime.h>
#include <cuda_bf16.h>
#include <cstdint>
#include <math.h>

#define BATCH 8
#define LSEQ  2048
#define DDIM  512

// ---------------------------------------------------------------------------
// Device-global scratch (module-load allocation; no runtime allocs).
// ---------------------------------------------------------------------------
static __device__ float g_P[(size_t)BATCH * LSEQ * LSEQ];                           // 128 MiB logits
static __device__ __align__(128) __nv_bfloat16 g_qh[(size_t)BATCH * LSEQ * DDIM];
static __device__ __align__(128) __nv_bfloat16 g_ql[(size_t)BATCH * LSEQ * DDIM];
static __device__ __align__(128) __nv_bfloat16 g_kh[(size_t)BATCH * LSEQ * DDIM];
static __device__ __align__(128) __nv_bfloat16 g_kl[(size_t)BATCH * LSEQ * DDIM];
static __device__ __align__(128) __nv_bfloat16 g_vth[(size_t)BATCH * DDIM * LSEQ];  // v transposed [b][d][j]
static __device__ __align__(128) __nv_bfloat16 g_vtl[(size_t)BATCH * DDIM * LSEQ];
static __device__ __align__(128) __nv_bfloat16 g_ah[(size_t)BATCH * LSEQ * LSEQ];   // attn hi/lo
static __device__ __align__(128) __nv_bfloat16 g_al[(size_t)BATCH * LSEQ * LSEQ];

// ---------------------------------------------------------------------------
// PTX helpers (architecture-agnostic: sm_80+ instructions only)
// ---------------------------------------------------------------------------
__device__ __forceinline__ uint32_t smem_u32(const void* p) {
    uint32_t a;
    asm("{ .reg .u64 t; cvta.to.shared.u64 t, %1; cvt.u32.u64 %0, t; }" : "=r"(a) : "l"(p));
    return a;
}
__device__ __forceinline__ void ldsm4(uint32_t* r, uint32_t addr) {
    asm volatile("ldmatrix.sync.aligned.m8n8.x4.shared.b16 {%0,%1,%2,%3}, [%4];"
                 : "=r"(r[0]), "=r"(r[1]), "=r"(r[2]), "=r"(r[3]) : "r"(addr));
}
#define MMA16816(d, a, b0, b1)                                                     \
    asm volatile("mma.sync.aligned.m16n8k16.row.col.f32.bf16.bf16.f32 "            \
                 "{%0,%1,%2,%3},{%4,%5,%6,%7},{%8,%9},{%0,%1,%2,%3};"              \
                 : "+f"((d)[0]), "+f"((d)[1]), "+f"((d)[2]), "+f"((d)[3])          \
                 : "r"((a)[0]), "r"((a)[1]), "r"((a)[2]), "r"((a)[3]),             \
                   "r"(b0), "r"(b1))
#define CP_ASYNC16(dst, src) \
    asm volatile("cp.async.cg.shared.global [%0], [%1], 16;" :: "r"(dst), "l"(src))
#define CP_COMMIT()  asm volatile("cp.async.commit_group;" ::: "memory")
#define CP_WAIT0()   asm volatile("cp.async.wait_group 0;" ::: "memory")

__device__ __forceinline__ void split2(float v, __nv_bfloat16& h, __nv_bfloat16& l) {
    h = __float2bfloat16(v);
    l = __float2bfloat16(v - __bfloat162float(h));
}

// ---------------------------------------------------------------------------
// Kernel 1: split projections. q,k stored [b][i][d] hi/lo; v stored transposed
// [b][d][j] hi/lo via smem tile transpose. Block handles 64(j) x 64(d).
// ---------------------------------------------------------------------------
__global__ __launch_bounds__(256) void split_kernel(const float* __restrict__ x,
                                                    const float* __restrict__ qw,
                                                    const float* __restrict__ kw,
                                                    const float* __restrict__ vw)
{
    __shared__ __nv_bfloat16 vh_s[64][66];
    __shared__ __nv_bfloat16 vl_s[64][66];

    const int b  = blockIdx.z;
    const int j0 = blockIdx.x * 64;
    const int d0 = blockIdx.y * 64;
    const int t  = threadIdx.x;

    union U4 { __nv_bfloat16 h[4]; uint2 u; };

#pragma unroll
    for (int it = 0; it < 4; ++it) {
        const int id = t + it * 256;
        const int r  = id >> 4;
        const int c  = (id & 15) * 4;
        const size_t gx = ((size_t)b * LSEQ + j0 + r) * DDIM + d0 + c;
        const size_t gw = (size_t)(j0 + r) * DDIM + d0 + c;
        const float4 xv = *(const float4*)(x  + gx);
        const float4 q4 = *(const float4*)(qw + gw);
        const float4 k4 = *(const float4*)(kw + gw);
        const float4 v4 = *(const float4*)(vw + gw);

        U4 qh, ql, kh, kl;
        split2(xv.x * q4.x, qh.h[0], ql.h[0]); split2(xv.y * q4.y, qh.h[1], ql.h[1]);
        split2(xv.z * q4.z, qh.h[2], ql.h[2]); split2(xv.w * q4.w, qh.h[3], ql.h[3]);
        split2(xv.x * k4.x, kh.h[0], kl.h[0]); split2(xv.y * k4.y, kh.h[1], kl.h[1]);
        split2(xv.z * k4.z, kh.h[2], kl.h[2]); split2(xv.w * k4.w, kh.h[3], kl.h[3]);
        *(uint2*)(g_qh + gx) = qh.u;  *(uint2*)(g_ql + gx) = ql.u;
        *(uint2*)(g_kh + gx) = kh.u;  *(uint2*)(g_kl + gx) = kl.u;

        __nv_bfloat16 vh0, vl0;
        split2(xv.x * v4.x, vh0, vl0); vh_s[r][c + 0] = vh0; vl_s[r][c + 0] = vl0;
        split2(xv.y * v4.y, vh0, vl0); vh_s[r][c + 1] = vh0; vl_s[r][c + 1] = vl0;
        split2(xv.z * v4.z, vh0, vl0); vh_s[r][c + 2] = vh0; vl_s[r][c + 2] = vl0;
        split2(xv.w * v4.w, vh0, vl0); vh_s[r][c + 3] = vh0; vl_s[r][c + 3] = vl0;
    }
    __syncthreads();

#pragma unroll
    for (int it = 0; it < 16; ++it) {
        const int id = t + it * 256;
        const int dr = id >> 6;
        const int jc = id & 63;
        const size_t go = ((size_t)b * DDIM + d0 + dr) * LSEQ + j0 + jc;
        g_vth[go] = vh_s[jc][dr];
        g_vtl[go] = vl_s[jc][dr];
    }
}

// ---------------------------------------------------------------------------
// Kernel 2/4: 3-product bf16 HMMA GEMM. D[m,n] = sum_k A[m,k]*B[n,k], with
// A = Ah+Al, B = Bh+Bl (lo*lo dropped). Block tile 128x128, K-chunk 32,
// cp.async double buffer, 8 warps in 2(m) x 4(n) grid, warp tile 64x32.
// MODE 0: QK (K=512) -> scaled logits into g_P.
// MODE 1: AV (K=2048, A = attention hi/lo, B = v transposed) -> Cout.
// ---------------------------------------------------------------------------
template <int MODE>
__global__ __launch_bounds__(256) void gemm3_kernel(float* __restrict__ Cout)
{
    extern __shared__ __align__(128) char dsm[];

    constexpr int K      = (MODE == 0) ? DDIM : LSEQ;
    constexpr int NC     = K / 32;
    constexpr int LDC    = (MODE == 0) ? LSEQ : DDIM;
    constexpr int STRIDE = 40;               // bf16 elems per smem row (32 + 8 pad)
    constexpr int TILE_B = 128 * STRIDE * 2; // 10240 bytes per tile
    constexpr int STAGE_B = 4 * TILE_B;      // 40960 bytes per stage
    const float scale = (MODE == 0) ? 0.3535533905932738f : 1.0f;

    const __nv_bfloat16* Ah = (MODE == 0) ? g_qh : g_ah;
    const __nv_bfloat16* Al = (MODE == 0) ? g_ql : g_al;
    const __nv_bfloat16* Bh = (MODE == 0) ? g_kh : g_vth;
    const __nv_bfloat16* Bl = (MODE == 0) ? g_kl : g_vtl;

    const int b  = blockIdx.z;
    const int n0 = blockIdx.x * 128;
    const int m0 = blockIdx.y * 128;
    const int t    = threadIdx.x;
    const int lane = t & 31;
    const int wid  = t >> 5;
    const int wm   = wid & 1;   // 0..1 -> 64-row slab
    const int wn   = wid >> 1;  // 0..3 -> 32-col slab

    const size_t bA = (MODE == 0) ? (size_t)LSEQ * DDIM : (size_t)LSEQ * LSEQ;
    const size_t bB = (MODE == 0) ? (size_t)LSEQ * DDIM : (size_t)DDIM * LSEQ;
    const size_t bC = (MODE == 0) ? (size_t)LSEQ * LSEQ : (size_t)LSEQ * DDIM;

    const __nv_bfloat16* pAh = Ah + b * bA + (size_t)m0 * K;
    const __nv_bfloat16* pAl = Al + b * bA + (size_t)m0 * K;
    const __nv_bfloat16* pBh = Bh + b * bB + (size_t)n0 * K;
    const __nv_bfloat16* pBl = Bl + b * bB + (size_t)n0 * K;
    float* Cb = ((MODE == 0) ? g_P : Cout) + b * bC + (size_t)m0 * LDC + n0;

    const uint32_t sb = smem_u32(dsm);

    // Prefetch one 128x32 hi/lo A+B chunk into stage (c&1) via cp.async.
    auto prefetch = [&](int c) {
        const int s  = c & 1;
        const int k0 = c * 32;
        const uint32_t st = sb + s * STAGE_B;
        const __nv_bfloat16* gs[4] = { pAh + k0, pAl + k0, pBh + k0, pBl + k0 };
#pragma unroll
        for (int tt = 0; tt < 4; ++tt) {
            const uint32_t tb = st + tt * TILE_B;
#pragma unroll
            for (int i = 0; i < 2; ++i) {
                const int li  = t + i * 256;        // 0..511 16B-lines
                const int row = li >> 2;
                const int seg = li & 3;
                const uint32_t dst = tb + row * (STRIDE * 2) + seg * 16;
                const void* src = gs[tt] + (size_t)row * K + seg * 8;
                CP_ASYNC16(dst, src);
            }
        }
        CP_COMMIT();
    };

    float acc[4][4][4];
#pragma unroll
    for (int mf = 0; mf < 4; ++mf)
#pragma unroll
        for (int nf = 0; nf < 4; ++nf)
#pragma unroll
            for (int i = 0; i < 4; ++i) acc[mf][nf][i] = 0.0f;

    const int lr  = lane & 15;        // ldmatrix row within 16
    const int lc8 = (lane >> 4) * 8;  // ldmatrix 8-col block

    prefetch(0);
    for (int c = 0; c < NC; ++c) {
        CP_WAIT0();
        __syncthreads();
        if (c + 1 < NC) prefetch(c + 1);

        const uint32_t st  = sb + (c & 1) * STAGE_B;
        const uint32_t sAh = st;
        const uint32_t sAl = st + TILE_B;
        const uint32_t sBh = st + 2 * TILE_B;
        const uint32_t sBl = st + 3 * TILE_B;

#pragma unroll
        for (int ks = 0; ks < 2; ++ks) {
            uint32_t ah[4][4], al[4][4];
#pragma unroll
            for (int mf = 0; mf < 4; ++mf) {
                const uint32_t off =
                    ((wm * 64 + mf * 16 + lr) * STRIDE + ks * 16 + lc8) * 2;
                ldsm4(ah[mf], sAh + off);
                ldsm4(al[mf], sAl + off);
            }
            uint32_t bh[2][4], bl[2][4];
#pragma unroll
            for (int p = 0; p < 2; ++p) {
                const uint32_t off =
                    ((wn * 32 + p * 16 + lr) * STRIDE + ks * 16 + lc8) * 2;
                ldsm4(bh[p], sBh + off);
                ldsm4(bl[p], sBl + off);
            }
#pragma unroll
            for (int mf = 0; mf < 4; ++mf) {
#pragma unroll
                for (int nf = 0; nf < 4; ++nf) {
                    const int p = nf >> 1, s2 = nf & 1;
                    MMA16816(acc[mf][nf], ah[mf], bh[p][s2], bh[p][s2 + 2]);
                    MMA16816(acc[mf][nf], ah[mf], bl[p][s2], bl[p][s2 + 2]);
                    MMA16816(acc[mf][nf], al[mf], bh[p][s2], bh[p][s2 + 2]);
                }
            }
        }
    }

    // Epilogue: direct float2 stores (d0,d1 -> row r, d2,d3 -> row r+8)
#pragma unroll
    for (int mf = 0; mf < 4; ++mf) {
#pragma unroll
        for (int nf = 0; nf < 4; ++nf) {
            const int r0 = wm * 64 + mf * 16 + (lane >> 2);
            const int cc = wn * 32 + nf * 8 + (lane & 3) * 2;
            float2 v0, v1;
            v0.x = acc[mf][nf][0] * scale; v0.y = acc[mf][nf][1] * scale;
            v1.x = acc[mf][nf][2] * scale; v1.y = acc[mf][nf][3] * scale;
            *(float2*)&Cb[(size_t)r0 * LDC + cc]       = v0;
            *(float2*)&Cb[(size_t)(r0 + 8) * LDC + cc] = v1;
        }
    }
}

// ---------------------------------------------------------------------------
// Kernel 3: row softmax over g_P, output written as bf16 hi/lo attention.
// ---------------------------------------------------------------------------
__global__ __launch_bounds__(256) void softmax_kernel()
{
    const size_t row = blockIdx.x;
    const float* p = g_P + row * LSEQ;
    const int t = threadIdx.x;

    __shared__ float red[256];

    float v[8];
    float mx = -1e30f;
#pragma unroll
    for (int i = 0; i < 8; ++i) {
        v[i] = p[t + i * 256];
        mx = fmaxf(mx, v[i]);
    }
    red[t] = mx;
    __syncthreads();
    for (int s = 128; s > 0; s >>= 1) {
        if (t < s) red[t] = fmaxf(red[t], red[t + s]);
        __syncthreads();
    }
    const float m = red[0];
    __syncthreads();

    float sum = 0.0f;
#pragma unroll
    for (int i = 0; i < 8; ++i) {
        v[i] = __expf(v[i] - m);
        sum += v[i];
    }
    red[t] = sum;
    __syncthreads();
    for (int s = 128; s > 0; s >>= 1) {
        if (t < s) red[t] += red[t + s];
        __syncthreads();
    }
    const float inv = 1.0f / red[0];
#pragma unroll
    for (int i = 0; i < 8; ++i) {
        const float a = v[i] * inv;
        __nv_bfloat16 h, l;
        split2(a, h, l);
        const size_t o = row * LSEQ + t + i * 256;
        g_ah[o] = h;
        g_al[o] = l;
    }
}

// ---------------------------------------------------------------------------
extern "C" void kernel_launch(void* const* d_in, const int* in_sizes, int n_in,
                              void* d_out, int out_size)
{
    const float* x  = (const float*)d_in[0];
    const float* qw = (const float*)d_in[1];
    const float* kw = (const float*)d_in[2];
    const float* vw = (const float*)d_in[3];
    float* out = (float*)d_out;

    constexpr int SMEM = 81920;
    cudaFuncSetAttribute(gemm3_kernel<0>, cudaFuncAttributeMaxDynamicSharedMemorySize, SMEM);
    cudaFuncSetAttribute(gemm3_kernel<1>, cudaFuncAttributeMaxDynamicSharedMemorySize, SMEM);

    split_kernel<<<dim3(LSEQ / 64, DDIM / 64, BATCH), 256>>>(x, qw, kw, vw);

    gemm3_kernel<0><<<dim3(LSEQ / 128, LSEQ / 128, BATCH), 256, SMEM>>>(nullptr);

    softmax_kernel<<<BATCH * LSEQ, 256>>>();

    gemm3_kernel<1><<<dim3(DDIM / 128, LSEQ / 128, BATCH), 256, SMEM>>>(out);
}

// round 4
// speedup vs baseline: 2.8632x; 1.1307x over previous
#include <cuda_runtime.h>
#include <cuda_bf16.h>
#include <cstdint>
#include <math.h>

#define BATCH 8
#define LSEQ  2048
#define DDIM  512

// ---------------------------------------------------------------------------
// Device-global scratch (module-load allocation; no runtime allocs).
// ---------------------------------------------------------------------------
static __device__ float g_P[(size_t)BATCH * LSEQ * LSEQ];                           // 128 MiB logits
static __device__ __align__(128) __nv_bfloat16 g_qh[(size_t)BATCH * LSEQ * DDIM];
static __device__ __align__(128) __nv_bfloat16 g_ql[(size_t)BATCH * LSEQ * DDIM];
static __device__ __align__(128) __nv_bfloat16 g_kh[(size_t)BATCH * LSEQ * DDIM];
static __device__ __align__(128) __nv_bfloat16 g_kl[(size_t)BATCH * LSEQ * DDIM];
static __device__ __align__(128) __nv_bfloat16 g_vth[(size_t)BATCH * DDIM * LSEQ];  // v transposed [b][d][j]
static __device__ __align__(128) __nv_bfloat16 g_vtl[(size_t)BATCH * DDIM * LSEQ];
static __device__ __align__(128) __nv_bfloat16 g_ah[(size_t)BATCH * LSEQ * LSEQ];   // attn hi/lo
static __device__ __align__(128) __nv_bfloat16 g_al[(size_t)BATCH * LSEQ * LSEQ];

// ---------------------------------------------------------------------------
// PTX helpers (sm_80+ only; base sm_103 target has no tcgen05)
// ---------------------------------------------------------------------------
__device__ __forceinline__ uint32_t smem_u32(const void* p) {
    uint32_t a;
    asm("{ .reg .u64 t; cvta.to.shared.u64 t, %1; cvt.u32.u64 %0, t; }" : "=r"(a) : "l"(p));
    return a;
}
__device__ __forceinline__ void ldsm4(uint32_t* r, uint32_t addr) {
    asm volatile("ldmatrix.sync.aligned.m8n8.x4.shared.b16 {%0,%1,%2,%3}, [%4];"
                 : "=r"(r[0]), "=r"(r[1]), "=r"(r[2]), "=r"(r[3]) : "r"(addr));
}
#define MMA16816(d, a, b0, b1)                                                     \
    asm volatile("mma.sync.aligned.m16n8k16.row.col.f32.bf16.bf16.f32 "            \
                 "{%0,%1,%2,%3},{%4,%5,%6,%7},{%8,%9},{%0,%1,%2,%3};"              \
                 : "+f"((d)[0]), "+f"((d)[1]), "+f"((d)[2]), "+f"((d)[3])          \
                 : "r"((a)[0]), "r"((a)[1]), "r"((a)[2]), "r"((a)[3]),             \
                   "r"(b0), "r"(b1))
#define CP_ASYNC16(dst, src) \
    asm volatile("cp.async.cg.shared.global [%0], [%1], 16;" :: "r"(dst), "l"(src))
#define CP_COMMIT()  asm volatile("cp.async.commit_group;" ::: "memory")
#define CP_WAIT1()   asm volatile("cp.async.wait_group 1;" ::: "memory")

__device__ __forceinline__ void split2(float v, __nv_bfloat16& h, __nv_bfloat16& l) {
    h = __float2bfloat16(v);
    l = __float2bfloat16(v - __bfloat162float(h));
}

// Swizzled byte offset within a 128-row x 64-byte tile.
// seg (16B unit, 0..3) is XORed with bits (row>>1)&3 -> conflict-free ldmatrix.
__device__ __forceinline__ uint32_t swz(int row, int seg) {
    return (uint32_t)(row * 64 + ((seg ^ ((row >> 1) & 3)) << 4));
}

// ---------------------------------------------------------------------------
// Kernel 1: split projections. q,k stored [b][i][d] hi/lo; v stored transposed
// [b][d][j] hi/lo via smem tile transpose. Block handles 64(j) x 64(d).
// ---------------------------------------------------------------------------
__global__ __launch_bounds__(256) void split_kernel(const float* __restrict__ x,
                                                    const float* __restrict__ qw,
                                                    const float* __restrict__ kw,
                                                    const float* __restrict__ vw)
{
    __shared__ __nv_bfloat16 vh_s[64][66];
    __shared__ __nv_bfloat16 vl_s[64][66];

    const int b  = blockIdx.z;
    const int j0 = blockIdx.x * 64;
    const int d0 = blockIdx.y * 64;
    const int t  = threadIdx.x;

    union U4 { __nv_bfloat16 h[4]; uint2 u; };

#pragma unroll
    for (int it = 0; it < 4; ++it) {
        const int id = t + it * 256;
        const int r  = id >> 4;
        const int c  = (id & 15) * 4;
        const size_t gx = ((size_t)b * LSEQ + j0 + r) * DDIM + d0 + c;
        const size_t gw = (size_t)(j0 + r) * DDIM + d0 + c;
        const float4 xv = *(const float4*)(x  + gx);
        const float4 q4 = *(const float4*)(qw + gw);
        const float4 k4 = *(const float4*)(kw + gw);
        const float4 v4 = *(const float4*)(vw + gw);

        U4 qh, ql, kh, kl;
        split2(xv.x * q4.x, qh.h[0], ql.h[0]); split2(xv.y * q4.y, qh.h[1], ql.h[1]);
        split2(xv.z * q4.z, qh.h[2], ql.h[2]); split2(xv.w * q4.w, qh.h[3], ql.h[3]);
        split2(xv.x * k4.x, kh.h[0], kl.h[0]); split2(xv.y * k4.y, kh.h[1], kl.h[1]);
        split2(xv.z * k4.z, kh.h[2], kl.h[2]); split2(xv.w * k4.w, kh.h[3], kl.h[3]);
        *(uint2*)(g_qh + gx) = qh.u;  *(uint2*)(g_ql + gx) = ql.u;
        *(uint2*)(g_kh + gx) = kh.u;  *(uint2*)(g_kl + gx) = kl.u;

        __nv_bfloat16 vh0, vl0;
        split2(xv.x * v4.x, vh0, vl0); vh_s[r][c + 0] = vh0; vl_s[r][c + 0] = vl0;
        split2(xv.y * v4.y, vh0, vl0); vh_s[r][c + 1] = vh0; vl_s[r][c + 1] = vl0;
        split2(xv.z * v4.z, vh0, vl0); vh_s[r][c + 2] = vh0; vl_s[r][c + 2] = vl0;
        split2(xv.w * v4.w, vh0, vl0); vh_s[r][c + 3] = vh0; vl_s[r][c + 3] = vl0;
    }
    __syncthreads();

#pragma unroll
    for (int it = 0; it < 16; ++it) {
        const int id = t + it * 256;
        const int dr = id >> 6;
        const int jc = id & 63;
        const size_t go = ((size_t)b * DDIM + d0 + dr) * LSEQ + j0 + jc;
        g_vth[go] = vh_s[jc][dr];
        g_vtl[go] = vl_s[jc][dr];
    }
}

// ---------------------------------------------------------------------------
// Kernel 2/4: 3-product bf16 HMMA GEMM. D[m,n] = sum_k A[m,k]*B[n,k], with
// A = Ah+Al, B = Bh+Bl (lo*lo dropped). Block tile 128x128, K-chunk 32,
// 3-stage cp.async pipeline, XOR-swizzled smem (no padding), 8 warps in
// 2(m) x 4(n) grid, warp tile 64x32, product-major MMA ordering.
// MODE 0: QK (K=512) -> scaled logits into g_P.
// MODE 1: AV (K=2048, A = attention hi/lo, B = v transposed) -> Cout.
// ---------------------------------------------------------------------------
template <int MODE>
__global__ __launch_bounds__(256, 2) void gemm3_kernel(float* __restrict__ Cout)
{
    extern __shared__ __align__(128) char dsm[];

    constexpr int K       = (MODE == 0) ? DDIM : LSEQ;
    constexpr int NC      = K / 32;
    constexpr int LDC     = (MODE == 0) ? LSEQ : DDIM;
    constexpr int TILE_B  = 128 * 64;      // 8192 bytes (128 rows x 32 bf16)
    constexpr int STAGE_B = 4 * TILE_B;    // 32768 bytes per stage
    const float scale = (MODE == 0) ? 0.3535533905932738f : 1.0f;

    const __nv_bfloat16* Ah = (MODE == 0) ? g_qh : g_ah;
    const __nv_bfloat16* Al = (MODE == 0) ? g_ql : g_al;
    const __nv_bfloat16* Bh = (MODE == 0) ? g_kh : g_vth;
    const __nv_bfloat16* Bl = (MODE == 0) ? g_kl : g_vtl;

    const int b  = blockIdx.z;
    const int n0 = blockIdx.x * 128;
    const int m0 = blockIdx.y * 128;
    const int t    = threadIdx.x;
    const int lane = t & 31;
    const int wid  = t >> 5;
    const int wm   = wid & 1;   // 0..1 -> 64-row slab
    const int wn   = wid >> 1;  // 0..3 -> 32-col slab

    const size_t bA = (MODE == 0) ? (size_t)LSEQ * DDIM : (size_t)LSEQ * LSEQ;
    const size_t bB = (MODE == 0) ? (size_t)LSEQ * DDIM : (size_t)DDIM * LSEQ;
    const size_t bC = (MODE == 0) ? (size_t)LSEQ * LSEQ : (size_t)LSEQ * DDIM;

    const __nv_bfloat16* pAh = Ah + b * bA + (size_t)m0 * K;
    const __nv_bfloat16* pAl = Al + b * bA + (size_t)m0 * K;
    const __nv_bfloat16* pBh = Bh + b * bB + (size_t)n0 * K;
    const __nv_bfloat16* pBl = Bl + b * bB + (size_t)n0 * K;
    float* Cb = ((MODE == 0) ? g_P : Cout) + b * bC + (size_t)m0 * LDC + n0;

    const uint32_t sb = smem_u32(dsm);

    // Prefetch one 128x32 hi/lo A+B chunk into stage slot s via cp.async.
    // Each tile: 512 16B lines; 256 threads -> 2 lines/thread/tile.
    auto prefetch = [&](int c, int s) {
        const int k0 = c * 32;
        const uint32_t st = sb + s * STAGE_B;
        const __nv_bfloat16* gs[4] = { pAh + k0, pAl + k0, pBh + k0, pBl + k0 };
#pragma unroll
        for (int tt = 0; tt < 4; ++tt) {
            const uint32_t tb = st + tt * TILE_B;
#pragma unroll
            for (int i = 0; i < 2; ++i) {
                const int li  = t + i * 256;        // 0..511
                const int row = li >> 2;
                const int seg = li & 3;
                const uint32_t dst = tb + swz(row, seg);
                const void* src = gs[tt] + (size_t)row * K + seg * 8;
                CP_ASYNC16(dst, src);
            }
        }
        CP_COMMIT();
    };

    float acc[4][4][4];
#pragma unroll
    for (int mf = 0; mf < 4; ++mf)
#pragma unroll
        for (int nf = 0; nf < 4; ++nf)
#pragma unroll
            for (int i = 0; i < 4; ++i) acc[mf][nf][i] = 0.0f;

    const int lr   = lane & 15;       // ldmatrix row within 16
    const int lseg = lane >> 4;       // 0/1: which 16B (8-col) half

    prefetch(0, 0);
    if (NC > 1) prefetch(1, 1);

    int s = 0;              // stage slot of chunk c
    for (int c = 0; c < NC; ++c) {
        CP_WAIT1();          // chunk c resident (c+1 may still be in flight)
        __syncthreads();     // all warps done reading slot that c+2 will use
        if (c + 2 < NC) {
            int s2 = s + 2; if (s2 >= 3) s2 -= 3;
            prefetch(c + 2, s2);
        }

        const uint32_t st  = sb + s * STAGE_B;
        const uint32_t sAh = st;
        const uint32_t sAl = st + TILE_B;
        const uint32_t sBh = st + 2 * TILE_B;
        const uint32_t sBl = st + 3 * TILE_B;

#pragma unroll
        for (int ks = 0; ks < 2; ++ks) {
            const int segk = ks * 2 + lseg;
            uint32_t ah[4][4], al[4][4];
#pragma unroll
            for (int mf = 0; mf < 4; ++mf) {
                const int row = wm * 64 + mf * 16 + lr;
                const uint32_t off = swz(row, segk);
                ldsm4(ah[mf], sAh + off);
                ldsm4(al[mf], sAl + off);
            }
            uint32_t bh[2][4], bl[2][4];
#pragma unroll
            for (int p = 0; p < 2; ++p) {
                const int row = wn * 32 + p * 16 + lr;
                const uint32_t off = swz(row, segk);
                ldsm4(bh[p], sBh + off);
                ldsm4(bl[p], sBl + off);
            }
            // product-major: 16 independent accumulators per pass
#pragma unroll
            for (int mf = 0; mf < 4; ++mf)
#pragma unroll
                for (int nf = 0; nf < 4; ++nf) {
                    const int p = nf >> 1, s2 = nf & 1;
                    MMA16816(acc[mf][nf], ah[mf], bh[p][s2], bh[p][s2 + 2]);
                }
#pragma unroll
            for (int mf = 0; mf < 4; ++mf)
#pragma unroll
                for (int nf = 0; nf < 4; ++nf) {
                    const int p = nf >> 1, s2 = nf & 1;
                    MMA16816(acc[mf][nf], ah[mf], bl[p][s2], bl[p][s2 + 2]);
                }
#pragma unroll
            for (int mf = 0; mf < 4; ++mf)
#pragma unroll
                for (int nf = 0; nf < 4; ++nf) {
                    const int p = nf >> 1, s2 = nf & 1;
                    MMA16816(acc[mf][nf], al[mf], bh[p][s2], bh[p][s2 + 2]);
                }
        }
        if (++s == 3) s = 0;
    }

    // Epilogue: direct float2 stores (d0,d1 -> row r, d2,d3 -> row r+8)
#pragma unroll
    for (int mf = 0; mf < 4; ++mf) {
#pragma unroll
        for (int nf = 0; nf < 4; ++nf) {
            const int r0 = wm * 64 + mf * 16 + (lane >> 2);
            const int cc = wn * 32 + nf * 8 + (lane & 3) * 2;
            float2 v0, v1;
            v0.x = acc[mf][nf][0] * scale; v0.y = acc[mf][nf][1] * scale;
            v1.x = acc[mf][nf][2] * scale; v1.y = acc[mf][nf][3] * scale;
            *(float2*)&Cb[(size_t)r0 * LDC + cc]       = v0;
            *(float2*)&Cb[(size_t)(r0 + 8) * LDC + cc] = v1;
        }
    }
}

// ---------------------------------------------------------------------------
// Kernel 3: row softmax over g_P, output written as bf16 hi/lo attention.
// ---------------------------------------------------------------------------
__global__ __launch_bounds__(256) void softmax_kernel()
{
    const size_t row = blockIdx.x;
    const float* p = g_P + row * LSEQ;
    const int t = threadIdx.x;

    __shared__ float red[256];

    float v[8];
    float mx = -1e30f;
#pragma unroll
    for (int i = 0; i < 8; ++i) {
        v[i] = p[t + i * 256];
        mx = fmaxf(mx, v[i]);
    }
    red[t] = mx;
    __syncthreads();
    for (int s = 128; s > 0; s >>= 1) {
        if (t < s) red[t] = fmaxf(red[t], red[t + s]);
        __syncthreads();
    }
    const float m = red[0];
    __syncthreads();

    float sum = 0.0f;
#pragma unroll
    for (int i = 0; i < 8; ++i) {
        v[i] = __expf(v[i] - m);
        sum += v[i];
    }
    red[t] = sum;
    __syncthreads();
    for (int s = 128; s > 0; s >>= 1) {
        if (t < s) red[t] += red[t + s];
        __syncthreads();
    }
    const float inv = 1.0f / red[0];
#pragma unroll
    for (int i = 0; i < 8; ++i) {
        const float a = v[i] * inv;
        __nv_bfloat16 h, l;
        split2(a, h, l);
        const size_t o = row * LSEQ + t + i * 256;
        g_ah[o] = h;
        g_al[o] = l;
    }
}

// ---------------------------------------------------------------------------
extern "C" void kernel_launch(void* const* d_in, const int* in_sizes, int n_in,
                              void* d_out, int out_size)
{
    const float* x  = (const float*)d_in[0];
    const float* qw = (const float*)d_in[1];
    const float* kw = (const float*)d_in[2];
    const float* vw = (const float*)d_in[3];
    float* out = (float*)d_out;

    constexpr int SMEM = 98304;   // 3 stages x 32 KB
    cudaFuncSetAttribute(gemm3_kernel<0>, cudaFuncAttributeMaxDynamicSharedMemorySize, SMEM);
    cudaFuncSetAttribute(gemm3_kernel<1>, cudaFuncAttributeMaxDynamicSharedMemorySize, SMEM);

    split_kernel<<<dim3(LSEQ / 64, DDIM / 64, BATCH), 256>>>(x, qw, kw, vw);

    gemm3_kernel<0><<<dim3(LSEQ / 128, LSEQ / 128, BATCH), 256, SMEM>>>(nullptr);

    softmax_kernel<<<BATCH * LSEQ, 256>>>();

    gemm3_kernel<1><<<dim3(DDIM / 128, LSEQ / 128, BATCH), 256, SMEM>>>(out);
}